// round 17
// baseline (speedup 1.0000x reference)
#include <cuda_runtime.h>
#include <cstdint>
#include <cfloat>

// Problem constants: z (2,64,8,64,64), embedding (4096,64)
#define CH 64
#define SPA 32768
#define NTOK 65536
#define KCODE 4096
#define OUT_ELEMS 4194304
#define TBLK 64
#define NBLK (NTOK / TBLK)      // 1024

// kB smem byte offsets (16B aligned)
#define OFF_WSM 0               // pre_w [o][c]                  16384
#define OFF_BSM 16384           // pre_b                           256
#define OFF_ZSM 16640           // z tile [64 c][64 tok]         16384
#define OFF_TSM 33024           // t tile [64 c][64 tok]         16384
#define OFF_ESM 49408           // e chunks 2 x [64 c][128 k]    65536
#define OFF_E2  114944          // e2 2 x 128 f                   1024
#define OFF_RV  115968          // argmin vals [8 w][64 t]        2048
#define OFF_RI  118016          // argmin idxs [8 w][64 t]        2048
#define OFF_IDX 120064          // final idx [64]                  256
#define OFF_LSM 120320          // loss partials [4][64]          1024
#define SMTOT   121344          // > 113.5KB => exactly 1 CTA/SM

typedef unsigned long long ull;

// -------- static device scratch (no cudaMalloc allowed) --------
__device__ __align__(16) float g_eT[KCODE / 128][64][128];   // [chunk][c][k]
__device__ __align__(16) float g_e2[KCODE];
__device__ __align__(16) float g_pe[KCODE * CH];             // emb @ post_w^T + post_b
__device__ float g_part[NBLK];

// -------- helpers (proven R2/R10/R15/R16) --------
__device__ __forceinline__ uint32_t smem_u32(const void* p) {
    uint32_t a;
    asm("{ .reg .u64 t; cvta.to.shared.u64 t, %1; cvt.u32.u64 %0, t; }" : "=r"(a) : "l"(p));
    return a;
}
__device__ __forceinline__ void cpa16(uint32_t dst, const void* src) {
    asm volatile("cp.async.cg.shared.global [%0], [%1], 16;" :: "r"(dst), "l"(src) : "memory");
}
#define CP_COMMIT() asm volatile("cp.async.commit_group;" ::: "memory")
#define CP_WAIT0()  asm volatile("cp.async.wait_group 0;" ::: "memory")
#define CP_WAIT1()  asm volatile("cp.async.wait_group 1;" ::: "memory")

__device__ __forceinline__ ull ffma2(ull a, ull b, ull c) {
    ull d;
    asm("fma.rn.f32x2 %0, %1, %2, %3;" : "=l"(d) : "l"(a), "l"(b), "l"(c));
    return d;
}
__device__ __forceinline__ ull dup2(float x) {
    ull d;
    unsigned u = __float_as_uint(x);
    asm("mov.b64 %0, {%1, %2};" : "=l"(d) : "r"(u), "r"(u));
    return d;
}
__device__ __forceinline__ float f2lo(ull v) { return __uint_as_float((unsigned)v); }
__device__ __forceinline__ float f2hi(ull v) { return __uint_as_float((unsigned)(v >> 32)); }

// ============================================================================
// kP: pe = emb @ post_w^T + post_b ; e2 ; transposed codebook g_eT.
// 1024 blocks x 256 thr; 4 codes per block, one shot (measured 14us).
// ============================================================================
__global__ void __launch_bounds__(256) kP(const float* __restrict__ emb,
                                          const float* __restrict__ post_w,
                                          const float* __restrict__ post_b) {
    __shared__ float wsm[64 * 65];
    __shared__ float esm[4][64];
    __shared__ float wred[4][2];
    int tid = threadIdx.x;
    int sub = tid >> 6;
    int o = tid & 63;
    int wh = (tid >> 5) & 1;
    int k = blockIdx.x * 4 + sub;

    for (int i = tid; i < 4096; i += 256)
        wsm[(i >> 6) * 65 + (i & 63)] = post_w[i];

    float v = emb[k * 64 + o];
    esm[sub][o] = v;
    float sq = v * v;
#pragma unroll
    for (int off = 16; off; off >>= 1)
        sq += __shfl_xor_sync(0xffffffffu, sq, off);
    if ((tid & 31) == 0) wred[sub][wh] = sq;
    __syncthreads();

    float acc = post_b[o];
#pragma unroll
    for (int c = 0; c < 64; c++)
        acc = fmaf(esm[sub][c], wsm[o * 65 + c], acc);
    g_pe[k * 64 + o] = acc;
    g_eT[k >> 7][o][k & 127] = v;
    if (o == 0) g_e2[k] = wred[sub][0] + wred[sub][1];
}

// ============================================================================
// kB: fused pre-conv + exact fp32 argmin + loss/gather/output epilogue.
// 1024 CTAs x 256 thr; 64 tokens/CTA; 1 CTA/SM -> 7 waves @98.9%.
// Measured fma-pipe law: T = 3*(#FFMA2) + (#FFMA), s.t. 2*(#FFMA) <= T.
// Optimal mix: a=7 FFMA2 + b=18 FFMA per channel -> 39 cyc (was 45).
// token0 = 4 F2 (codes 0-7) + 8 F (8-15); token1 = 3 F2 (0-5) + 10 F (6-15).
// Identical fp32 op sequence per score; ascending-k strict-< tie-break intact.
// ============================================================================
__global__ void __launch_bounds__(256) kB(const float* __restrict__ z,
                                          const float* __restrict__ emb,
                                          const float* __restrict__ pre_w,
                                          const float* __restrict__ pre_b,
                                          float* __restrict__ dout) {
    extern __shared__ __align__(16) char sm[];
    uint32_t smb = smem_u32(sm);
    float* wsm  = (float*)(sm + OFF_WSM);
    float* bsm  = (float*)(sm + OFF_BSM);
    float* zsm  = (float*)(sm + OFF_ZSM);
    float* tsm  = (float*)(sm + OFF_TSM);
    float* rv   = (float*)(sm + OFF_RV);
    int*   ri   = (int*)  (sm + OFF_RI);
    int*   idxs = (int*)  (sm + OFF_IDX);
    float* lsm  = (float*)(sm + OFF_LSM);

    int tid = threadIdx.x;
    int ty = tid >> 5;              // warp: 16-code stripe
    int tx = tid & 31;              // lane: token pair (2tx, 2tx+1)
    int n0 = blockIdx.x * TBLK;
    int b  = n0 >> 15;
    int s0 = n0 & 32767;

    // ---- prologue cp.async: group0 = {w, b, z, e chunk0, e2_0}; group1 = {chunk1, e2_1}
    const char* zb = (const char*)z + ((size_t)b * (CH * SPA) + s0) * 4;
#pragma unroll
    for (int it = 0; it < 4; it++)
        cpa16(smb + OFF_WSM + (tid + it * 256) * 16, (const char*)pre_w + (tid + it * 256) * 16);
    if (tid < 16) cpa16(smb + OFF_BSM + tid * 16, (const char*)pre_b + tid * 16);
#pragma unroll
    for (int it = 0; it < 4; it++) {
        int ix = tid + it * 256;    // 1024 segs: c = ix>>4, seg = ix&15
        cpa16(smb + OFF_ZSM + ix * 16, zb + (size_t)(ix >> 4) * SPA * 4 + (ix & 15) * 16);
    }
#pragma unroll
    for (int it = 0; it < 8; it++)
        cpa16(smb + OFF_ESM + (tid + it * 256) * 16, (const char*)g_eT + (tid + it * 256) * 16);
    if (tid < 32) cpa16(smb + OFF_E2 + tid * 16, (const char*)g_e2 + tid * 16);
    CP_COMMIT();
#pragma unroll
    for (int it = 0; it < 8; it++)
        cpa16(smb + OFF_ESM + 32768 + (tid + it * 256) * 16,
              (const char*)g_eT + 32768 + (tid + it * 256) * 16);
    if (tid < 32) cpa16(smb + OFF_E2 + 512 + tid * 16, (const char*)(g_e2 + 128) + tid * 16);
    CP_COMMIT();
    CP_WAIT1();                     // group0 landed
    __syncthreads();

    // ---- phase 0: pre-conv for this block's 64 tokens -> tsm[c][tok]
    {
        int g = tid >> 6;           // 0..3 -> 16 output channels
        int j = tid & 63;           // token
        float acc16[16];
#pragma unroll
        for (int o = 0; o < 16; o++) acc16[o] = bsm[g * 16 + o];
#pragma unroll 8
        for (int c = 0; c < 64; c++) {
            float zv = zsm[c * 64 + j];
#pragma unroll
            for (int o = 0; o < 16; o++)
                acc16[o] = fmaf(zv, wsm[(g * 16 + o) * 64 + c], acc16[o]);
        }
#pragma unroll
        for (int o = 0; o < 16; o++) tsm[(g * 16 + o) * 64 + j] = acc16[o];
    }
    __syncthreads();

    // ---- main loop: 32 chunks of 128 codes, exact fp32, double-buffered
    float best0 = FLT_MAX, best1 = FLT_MAX;
    int bi0 = 0x7fffffff, bi1 = 0x7fffffff;

    for (int i = 0; i < 32; i++) {
        if (i < 31) { CP_WAIT1(); } else { CP_WAIT0(); }
        __syncthreads();
        int buf = i & 1;
        const float* erow = (const float*)(sm + OFF_ESM + buf * 32768) + ty * 16;
        const float* e2b  = (const float*)(sm + OFF_E2 + buf * 512);

        // a=7 FFMA2 + b=18 FFMA per channel:
        // token0: 4 pairs (codes 0-7) + 8 scalars (codes 8-15)
        // token1: 3 pairs (codes 0-5) + 10 scalars (codes 6-15)
        ull a20[4], a21[3];
        float s0[8], s1[10];
#pragma unroll
        for (int j = 0; j < 4; j++) a20[j] = 0ull;
#pragma unroll
        for (int j = 0; j < 3; j++) a21[j] = 0ull;
#pragma unroll
        for (int j = 0; j < 8; j++) s0[j] = 0.0f;
#pragma unroll
        for (int j = 0; j < 10; j++) s1[j] = 0.0f;

#pragma unroll 8
        for (int c = 0; c < 64; c++) {
            float2 tv = *(const float2*)(tsm + c * 64 + 2 * tx);
            ull td0 = dup2(tv.x);
            ull td1 = dup2(tv.y);
            const ulonglong2* ep = (const ulonglong2*)(erow + c * 128);
            ulonglong2 ea = ep[0];      // codes 0..3 (warp-uniform LDS)
            ulonglong2 eb = ep[1];      // codes 4..7
            const ulonglong2* ep2 = (const ulonglong2*)(erow + c * 128 + 8);
            ulonglong2 ec = ep2[0];     // codes 8..11
            ulonglong2 ed = ep2[1];     // codes 12..15
            // token0 pairs: codes 0..7
            a20[0] = ffma2(td0, ea.x, a20[0]);
            a20[1] = ffma2(td0, ea.y, a20[1]);
            a20[2] = ffma2(td0, eb.x, a20[2]);
            a20[3] = ffma2(td0, eb.y, a20[3]);
            // token1 pairs: codes 0..5
            a21[0] = ffma2(td1, ea.x, a21[0]);
            a21[1] = ffma2(td1, ea.y, a21[1]);
            a21[2] = ffma2(td1, eb.x, a21[2]);
            // token0 scalars: codes 8..15
            s0[0] = fmaf(tv.x, f2lo(ec.x), s0[0]);
            s0[1] = fmaf(tv.x, f2hi(ec.x), s0[1]);
            s0[2] = fmaf(tv.x, f2lo(ec.y), s0[2]);
            s0[3] = fmaf(tv.x, f2hi(ec.y), s0[3]);
            s0[4] = fmaf(tv.x, f2lo(ed.x), s0[4]);
            s0[5] = fmaf(tv.x, f2hi(ed.x), s0[5]);
            s0[6] = fmaf(tv.x, f2lo(ed.y), s0[6]);
            s0[7] = fmaf(tv.x, f2hi(ed.y), s0[7]);
            // token1 scalars: codes 6..15
            s1[0] = fmaf(tv.y, f2lo(eb.y), s1[0]);
            s1[1] = fmaf(tv.y, f2hi(eb.y), s1[1]);
            s1[2] = fmaf(tv.y, f2lo(ec.x), s1[2]);
            s1[3] = fmaf(tv.y, f2hi(ec.x), s1[3]);
            s1[4] = fmaf(tv.y, f2lo(ec.y), s1[4]);
            s1[5] = fmaf(tv.y, f2hi(ec.y), s1[5]);
            s1[6] = fmaf(tv.y, f2lo(ed.x), s1[6]);
            s1[7] = fmaf(tv.y, f2hi(ed.x), s1[7]);
            s1[8] = fmaf(tv.y, f2lo(ed.y), s1[8]);
            s1[9] = fmaf(tv.y, f2hi(ed.y), s1[9]);
        }

        // score = e2 - 2*dot ; ascending k per token, strict < (jnp tie-break)
        int kb = i * 128 + ty * 16;
        // token0: pairs codes 0..7, then scalars codes 8..15
#pragma unroll
        for (int j = 0; j < 4; j++) {
            float sA = fmaf(f2lo(a20[j]), -2.0f, e2b[ty * 16 + 2 * j]);
            float sB = fmaf(f2hi(a20[j]), -2.0f, e2b[ty * 16 + 2 * j + 1]);
            if (sA < best0) { best0 = sA; bi0 = kb + 2 * j; }
            if (sB < best0) { best0 = sB; bi0 = kb + 2 * j + 1; }
        }
#pragma unroll
        for (int j = 0; j < 8; j++) {
            float sv = fmaf(s0[j], -2.0f, e2b[ty * 16 + 8 + j]);
            if (sv < best0) { best0 = sv; bi0 = kb + 8 + j; }
        }
        // token1: pairs codes 0..5, then scalars codes 6..15
#pragma unroll
        for (int j = 0; j < 3; j++) {
            float sA = fmaf(f2lo(a21[j]), -2.0f, e2b[ty * 16 + 2 * j]);
            float sB = fmaf(f2hi(a21[j]), -2.0f, e2b[ty * 16 + 2 * j + 1]);
            if (sA < best1) { best1 = sA; bi1 = kb + 2 * j; }
            if (sB < best1) { best1 = sB; bi1 = kb + 2 * j + 1; }
        }
#pragma unroll
        for (int j = 0; j < 10; j++) {
            float sv = fmaf(s1[j], -2.0f, e2b[ty * 16 + 6 + j]);
            if (sv < best1) { best1 = sv; bi1 = kb + 6 + j; }
        }

        __syncthreads();            // all warps done reading buf
        if (i + 2 < 32) {
            const char* es = (const char*)g_eT + (size_t)(i + 2) * 32768;
#pragma unroll
            for (int it = 0; it < 8; it++)
                cpa16(smb + OFF_ESM + buf * 32768 + (tid + it * 256) * 16,
                      es + (tid + it * 256) * 16);
            if (tid < 32)
                cpa16(smb + OFF_E2 + buf * 512 + tid * 16,
                      (const char*)(g_e2 + (i + 2) * 128) + tid * 16);
            CP_COMMIT();
        }
    }

    // ---- cross-warp argmin reduce per token (lowest-index tie-break)
    rv[ty * 64 + 2 * tx]     = best0;
    rv[ty * 64 + 2 * tx + 1] = best1;
    ri[ty * 64 + 2 * tx]     = bi0;
    ri[ty * 64 + 2 * tx + 1] = bi1;
    __syncthreads();
    if (tid < 64) {
        float bv = FLT_MAX;
        int bk = 0x7fffffff;
#pragma unroll
        for (int w = 0; w < 8; w++) {
            float v = rv[w * 64 + tid];
            int k = ri[w * 64 + tid];
            if (v < bv || (v == bv && k < bk)) { bv = v; bk = k; }
        }
        idxs[tid] = bk;
    }
    __syncthreads();

    // ---- fused output epilogue: loss partial + pe gather + idx out
    {
        int g = tid >> 6;           // 16 channels
        int j = tid & 63;           // token
        int myidx = idxs[j];
        const float4* er = (const float4*)(emb + (size_t)myidx * 64 + g * 16);
        const float4* pr = (const float4*)(g_pe + (size_t)myidx * 64 + g * 16);
        float lp = 0.0f;
        float* op = dout + (size_t)b * (CH * SPA) + (size_t)(g * 16) * SPA + s0 + j;
#pragma unroll
        for (int q4 = 0; q4 < 4; q4++) {
            float4 e4 = er[q4];
            float4 p4 = pr[q4];
            int o = q4 * 4;
            float d;
            d = e4.x - tsm[(g * 16 + o + 0) * 64 + j]; lp = fmaf(d, d, lp);
            d = e4.y - tsm[(g * 16 + o + 1) * 64 + j]; lp = fmaf(d, d, lp);
            d = e4.z - tsm[(g * 16 + o + 2) * 64 + j]; lp = fmaf(d, d, lp);
            d = e4.w - tsm[(g * 16 + o + 3) * 64 + j]; lp = fmaf(d, d, lp);
            op[(size_t)(o + 0) * SPA] = p4.x;
            op[(size_t)(o + 1) * SPA] = p4.y;
            op[(size_t)(o + 2) * SPA] = p4.z;
            op[(size_t)(o + 3) * SPA] = p4.w;
        }
        lsm[g * 64 + j] = lp;
        if (g == 0) dout[OUT_ELEMS + 2 + n0 + j] = (float)myidx;
    }
    __syncthreads();
    if (tid < 64) {
        float s = lsm[tid] + lsm[64 + tid] + lsm[128 + tid] + lsm[192 + tid];
        rv[tid] = s;
    }
    __syncthreads();
    if (tid == 0) {
        float s = 0.0f;
#pragma unroll
        for (int j = 0; j < 64; j++) s += rv[j];
        g_part[blockIdx.x] = s;
    }
}

// ============================================================================
// kD: deterministic final loss reduction over 1024 block partials
// ============================================================================
__global__ void kD(float* __restrict__ dout) {
    __shared__ float red[256];
    int tid = threadIdx.x;
    float s = 0.0f;
#pragma unroll
    for (int j = 0; j < 4; j++) s += g_part[tid + j * 256];
    red[tid] = s;
    __syncthreads();
#pragma unroll
    for (int st = 128; st > 0; st >>= 1) {
        if (tid < st) red[tid] += red[tid + st];
        __syncthreads();
    }
    if (tid == 0) {
        float m = red[0] / (float)OUT_ELEMS;
        dout[OUT_ELEMS]     = m;   // codebook_loss
        dout[OUT_ELEMS + 1] = m;   // commitment_loss (same forward value)
    }
}

// ============================================================================
extern "C" void kernel_launch(void* const* d_in, const int* in_sizes, int n_in,
                              void* d_out, int out_size) {
    const float* z      = (const float*)d_in[0];
    const float* emb    = (const float*)d_in[1];
    const float* pre_w  = (const float*)d_in[2];
    const float* pre_b  = (const float*)d_in[3];
    const float* post_w = (const float*)d_in[4];
    const float* post_b = (const float*)d_in[5];
    float* dout = (float*)d_out;

    cudaFuncSetAttribute(kB, cudaFuncAttributeMaxDynamicSharedMemorySize, SMTOT);

    kP<<<KCODE / 4, 256>>>(emb, post_w, post_b);
    kB<<<NBLK, 256, SMTOT>>>(z, emb, pre_w, pre_b, dout);
    kD<<<1, 256>>>(dout);
}